// round 1
// baseline (speedup 1.0000x reference)
#include <cuda_runtime.h>
#include <cuda_bf16.h>

#define BB 4
#define TT 4096
#define DD 768
#define HH 64
#define BT (BB*TT)

// Scratch for projected Q, K, V (fp32). 3 x 4 MB static device arrays.
__device__ float g_Q[BT * HH];
__device__ float g_K[BT * HH];
__device__ float g_V[BT * HH];

// ---------------------------------------------------------------------------
// Kernel 1: fused QKV projection.  C[m] = x @ W[m], x:[BT,768], W:[768,64].
// Block: 64 rows x 192 cols (Q|K|V), 256 threads, 4x4 microtile per matrix.
// ---------------------------------------------------------------------------
__global__ __launch_bounds__(256) void qkv_kernel(
    const float* __restrict__ x,
    const float* __restrict__ Wq,
    const float* __restrict__ Wk,
    const float* __restrict__ Wv)
{
    __shared__ float xs[64][17];        // 64 rows x 16 k, padded
    __shared__ float ws[3][16][64];     // 3 mats x 16 k x 64 cols

    const int tid = threadIdx.x;
    const int ti  = tid >> 4;           // 0..15
    const int tj  = tid & 15;           // 0..15
    const int r0  = ti * 4;
    const int row0 = blockIdx.x * 64;

    float acc[3][4][4];
    #pragma unroll
    for (int m = 0; m < 3; m++)
        #pragma unroll
        for (int i = 0; i < 4; i++)
            #pragma unroll
            for (int c = 0; c < 4; c++)
                acc[m][i][c] = 0.0f;

    // precompute load indices
    const int xr  = tid >> 2;           // 0..63
    const int xk  = (tid & 3) * 4;      // 0,4,8,12
    const int wk  = tid >> 4;           // 0..15
    const int wc  = (tid & 15) * 4;     // 0..60

    for (int k0 = 0; k0 < DD; k0 += 16) {
        __syncthreads();
        // stage x tile: 64 x 16
        {
            float4 xv = *(const float4*)&x[(size_t)(row0 + xr) * DD + k0 + xk];
            xs[xr][xk + 0] = xv.x;
            xs[xr][xk + 1] = xv.y;
            xs[xr][xk + 2] = xv.z;
            xs[xr][xk + 3] = xv.w;
        }
        // stage W tiles: 3 x 16 x 64
        {
            *(float4*)&ws[0][wk][wc] = *(const float4*)&Wq[(size_t)(k0 + wk) * HH + wc];
            *(float4*)&ws[1][wk][wc] = *(const float4*)&Wk[(size_t)(k0 + wk) * HH + wc];
            *(float4*)&ws[2][wk][wc] = *(const float4*)&Wv[(size_t)(k0 + wk) * HH + wc];
        }
        __syncthreads();

        #pragma unroll
        for (int kk = 0; kk < 16; kk++) {
            float xv[4];
            #pragma unroll
            for (int ri = 0; ri < 4; ri++) xv[ri] = xs[r0 + ri][kk];
            #pragma unroll
            for (int m = 0; m < 3; m++) {
                float4 wv = *(const float4*)&ws[m][kk][tj * 4];
                #pragma unroll
                for (int ri = 0; ri < 4; ri++) {
                    acc[m][ri][0] = fmaf(xv[ri], wv.x, acc[m][ri][0]);
                    acc[m][ri][1] = fmaf(xv[ri], wv.y, acc[m][ri][1]);
                    acc[m][ri][2] = fmaf(xv[ri], wv.z, acc[m][ri][2]);
                    acc[m][ri][3] = fmaf(xv[ri], wv.w, acc[m][ri][3]);
                }
            }
        }
    }

    // store
    #pragma unroll
    for (int m = 0; m < 3; m++) {
        float* gout = (m == 0) ? g_Q : ((m == 1) ? g_K : g_V);
        #pragma unroll
        for (int ri = 0; ri < 4; ri++) {
            float4 o = make_float4(acc[m][ri][0], acc[m][ri][1],
                                   acc[m][ri][2], acc[m][ri][3]);
            *(float4*)&gout[(size_t)(row0 + r0 + ri) * HH + tj * 4] = o;
        }
    }
}

// ---------------------------------------------------------------------------
// Kernel 2: causal flash attention, fp32, online softmax.
// Block = 64 queries x full head (64). 256 threads as 16x16, 4x4 microtiles.
// XOR swizzle on smem quad index for conflict-light float4 reads.
// ---------------------------------------------------------------------------
__global__ __launch_bounds__(256) void attn_kernel(float* __restrict__ out)
{
    __shared__ float Qs[64 * 64];
    __shared__ float Ks[64 * 64];
    __shared__ float Vs[64 * 64];
    __shared__ float Ps[64 * 65];

    const int tid = threadIdx.x;
    const int ti  = tid >> 4;            // 0..15 -> rows r0..r0+3
    const int tj  = tid & 15;            // 0..15 -> score cols 4tj.. / out cols 4tj..
    const int r0  = ti * 4;

    const int b  = blockIdx.y;
    const int qt = gridDim.x - 1 - blockIdx.x;   // reverse: heavy blocks first
    const int q0 = qt * 64;
    const size_t base = (size_t)b * TT * HH;

    // Load Q tile once, pre-scaled by 1/sqrt(H)=0.125, swizzled.
    #pragma unroll
    for (int i = 0; i < 4; i++) {
        int f   = tid + i * 256;
        int row = f >> 4;
        int q   = f & 15;
        float4 v = *(const float4*)&g_Q[base + (size_t)(q0 + row) * HH + q * 4];
        v.x *= 0.125f; v.y *= 0.125f; v.z *= 0.125f; v.w *= 0.125f;
        int sq = (q ^ (row >> 2)) << 2;
        *(float4*)&Qs[row * 64 + sq] = v;
    }

    float m[4], l[4], O[4][4];
    #pragma unroll
    for (int ri = 0; ri < 4; ri++) {
        m[ri] = -1.0e30f;
        l[ri] = 0.0f;
        #pragma unroll
        for (int c = 0; c < 4; c++) O[ri][c] = 0.0f;
    }

    const int ntiles = qt + 1;
    for (int kt = 0; kt < ntiles; kt++) {
        const int jbase = kt * 64;
        __syncthreads();   // previous tile fully consumed
        // stage K, V tiles (swizzled)
        #pragma unroll
        for (int i = 0; i < 4; i++) {
            int f   = tid + i * 256;
            int row = f >> 4;
            int q   = f & 15;
            int sq  = (q ^ (row >> 2)) << 2;
            size_t g = base + (size_t)(jbase + row) * HH + q * 4;
            *(float4*)&Ks[row * 64 + sq] = *(const float4*)&g_K[g];
            *(float4*)&Vs[row * 64 + sq] = *(const float4*)&g_V[g];
        }
        __syncthreads();

        // ---- S = Q K^T (4x4 microtile, k-vectorized by 4) ----
        float acc[4][4];
        #pragma unroll
        for (int ri = 0; ri < 4; ri++)
            #pragma unroll
            for (int cj = 0; cj < 4; cj++) acc[ri][cj] = 0.0f;

        #pragma unroll
        for (int kq = 0; kq < 16; kq++) {
            float4 qv[4], kv[4];
            #pragma unroll
            for (int ri = 0; ri < 4; ri++)
                qv[ri] = *(const float4*)&Qs[(r0 + ri) * 64 + ((kq ^ ti) << 2)];
            #pragma unroll
            for (int cj = 0; cj < 4; cj++)
                kv[cj] = *(const float4*)&Ks[(4 * tj + cj) * 64 + ((kq ^ tj) << 2)];
            #pragma unroll
            for (int ri = 0; ri < 4; ri++)
                #pragma unroll
                for (int cj = 0; cj < 4; cj++) {
                    acc[ri][cj] = fmaf(qv[ri].x, kv[cj].x, acc[ri][cj]);
                    acc[ri][cj] = fmaf(qv[ri].y, kv[cj].y, acc[ri][cj]);
                    acc[ri][cj] = fmaf(qv[ri].z, kv[cj].z, acc[ri][cj]);
                    acc[ri][cj] = fmaf(qv[ri].w, kv[cj].w, acc[ri][cj]);
                }
        }

        const bool diag = (kt == qt);   // only diagonal tile needs masking

        // ---- online softmax per owned row ----
        #pragma unroll
        for (int ri = 0; ri < 4; ri++) {
            const int r = r0 + ri;
            if (diag) {
                #pragma unroll
                for (int cj = 0; cj < 4; cj++)
                    acc[ri][cj] = (4 * tj + cj > r) ? -1.0e30f : acc[ri][cj];
            }
            float mx = fmaxf(fmaxf(acc[ri][0], acc[ri][1]),
                             fmaxf(acc[ri][2], acc[ri][3]));
            mx = fmaxf(mx, __shfl_xor_sync(0xffffffffu, mx, 1));
            mx = fmaxf(mx, __shfl_xor_sync(0xffffffffu, mx, 2));
            mx = fmaxf(mx, __shfl_xor_sync(0xffffffffu, mx, 4));
            mx = fmaxf(mx, __shfl_xor_sync(0xffffffffu, mx, 8));

            float newm = fmaxf(m[ri], mx);
            float corr = __expf(m[ri] - newm);

            float ls = 0.0f;
            #pragma unroll
            for (int cj = 0; cj < 4; cj++) {
                float p = __expf(acc[ri][cj] - newm);
                ls += p;
                Ps[r * 65 + 4 * tj + cj] = p;
            }
            ls += __shfl_xor_sync(0xffffffffu, ls, 1);
            ls += __shfl_xor_sync(0xffffffffu, ls, 2);
            ls += __shfl_xor_sync(0xffffffffu, ls, 4);
            ls += __shfl_xor_sync(0xffffffffu, ls, 8);

            l[ri] = l[ri] * corr + ls;
            m[ri] = newm;
            #pragma unroll
            for (int c = 0; c < 4; c++) O[ri][c] *= corr;
        }
        __syncthreads();   // Ps visible to all

        // ---- O += P @ V ----
        #pragma unroll
        for (int j4 = 0; j4 < 64; j4 += 4) {
            float4 vv[4];
            const int sw = (j4 >> 2);
            #pragma unroll
            for (int jj = 0; jj < 4; jj++)
                vv[jj] = *(const float4*)&Vs[(j4 + jj) * 64 + ((tj ^ sw) << 2)];
            #pragma unroll
            for (int ri = 0; ri < 4; ri++) {
                float p0 = Ps[(r0 + ri) * 65 + j4 + 0];
                float p1 = Ps[(r0 + ri) * 65 + j4 + 1];
                float p2 = Ps[(r0 + ri) * 65 + j4 + 2];
                float p3 = Ps[(r0 + ri) * 65 + j4 + 3];
                O[ri][0] = fmaf(p0, vv[0].x, O[ri][0]);
                O[ri][1] = fmaf(p0, vv[0].y, O[ri][1]);
                O[ri][2] = fmaf(p0, vv[0].z, O[ri][2]);
                O[ri][3] = fmaf(p0, vv[0].w, O[ri][3]);
                O[ri][0] = fmaf(p1, vv[1].x, O[ri][0]);
                O[ri][1] = fmaf(p1, vv[1].y, O[ri][1]);
                O[ri][2] = fmaf(p1, vv[1].z, O[ri][2]);
                O[ri][3] = fmaf(p1, vv[1].w, O[ri][3]);
                O[ri][0] = fmaf(p2, vv[2].x, O[ri][0]);
                O[ri][1] = fmaf(p2, vv[2].y, O[ri][1]);
                O[ri][2] = fmaf(p2, vv[2].z, O[ri][2]);
                O[ri][3] = fmaf(p2, vv[2].w, O[ri][3]);
                O[ri][0] = fmaf(p3, vv[3].x, O[ri][0]);
                O[ri][1] = fmaf(p3, vv[3].y, O[ri][1]);
                O[ri][2] = fmaf(p3, vv[3].z, O[ri][2]);
                O[ri][3] = fmaf(p3, vv[3].w, O[ri][3]);
            }
        }
    }

    // epilogue: normalize and store
    #pragma unroll
    for (int ri = 0; ri < 4; ri++) {
        float inv = 1.0f / l[ri];
        float4 o = make_float4(O[ri][0] * inv, O[ri][1] * inv,
                               O[ri][2] * inv, O[ri][3] * inv);
        *(float4*)&out[base + (size_t)(q0 + r0 + ri) * HH + tj * 4] = o;
    }
}

// ---------------------------------------------------------------------------
extern "C" void kernel_launch(void* const* d_in, const int* in_sizes, int n_in,
                              void* d_out, int out_size)
{
    const float* x  = (const float*)d_in[0];
    const float* Wq = (const float*)d_in[1];
    const float* Wk = (const float*)d_in[2];
    const float* Wv = (const float*)d_in[3];
    float* out = (float*)d_out;

    qkv_kernel<<<BT / 64, 256>>>(x, Wq, Wk, Wv);
    attn_kernel<<<dim3(TT / 64, BB), 256>>>(out);
}